// round 7
// baseline (speedup 1.0000x reference)
#include <cuda_runtime.h>
#include <cstdint>

#define B_   256
#define T_   2048
#define IN_  128
#define H_   64
#define G_   256   // 4*H

// Scratch (allocation-free rule: static __device__ array)
__device__ float g_xp[(size_t)B_ * T_ * G_];   // precomputed x@W_ih1^T + b_ih1 + b_hh1

typedef unsigned long long u64;

// ---------------- helpers ----------------
__device__ __forceinline__ void ffma2(u64& d, u64 a, u64 b) {
    asm("fma.rn.f32x2 %0, %1, %2, %0;" : "+l"(d) : "l"(a), "l"(b));
}
__device__ __forceinline__ float2 unpk(u64 p) {
    float2 r;
    asm("mov.b64 {%0, %1}, %2;" : "=f"(r.x), "=f"(r.y) : "l"(p));
    return r;
}
__device__ __forceinline__ float sigf(float x) {
    return __fdividef(1.0f, 1.0f + __expf(-x));
}
__device__ __forceinline__ float tanhf_(float x) {
    float a = fabsf(x);
    float e = __expf(2.0f * a);                 // inf-safe
    float r = 1.0f - __fdividef(2.0f, e + 1.0f);
    return copysignf(r, x);
}

// ---------------- kernel 1: xp = x @ W_ih1^T + b_ih1 + b_hh1 ----------------
// Reads W directly (row-major, k contiguous); k-paired f32x2 accumulators.
// M = B*T = 524288, N = 256, K = 128. BM=64, BN=64, 256 threads, 4x4 tile.
__global__ __launch_bounds__(256) void xp_gemm(const float* __restrict__ x,
                                               const float* __restrict__ W,
                                               const float* __restrict__ bih,
                                               const float* __restrict__ bhh) {
    __shared__ float Xs[64][128];              // 32 KB
    int tid = threadIdx.x;
    size_t mbase = (size_t)blockIdx.x * 64;
    int nbase = blockIdx.y * 64;

    const float* xg = x + mbase * IN_;
#pragma unroll
    for (int i = 0; i < 8; i++) {
        int idx = tid + i * 256;
        int m = idx >> 5, k4 = (idx & 31) << 2;
        *(float4*)&Xs[m][k4] = *(const float4*)(xg + m * IN_ + k4);
    }
    __syncthreads();

    int tx = tid & 15, ty = tid >> 4;
    int n0 = nbase + tx * 4;
    int m0 = ty * 4;

    u64 acc[4][4];   // [m][n], k-paired
#pragma unroll
    for (int i = 0; i < 4; i++)
#pragma unroll
        for (int j = 0; j < 4; j++) acc[i][j] = 0ull;

#pragma unroll 4
    for (int k4 = 0; k4 < IN_; k4 += 4) {      // 32 iters, 4 k per iter
        u64 wv[4][2];                          // W[n0+j][k4..k4+4) as 2 k-pairs
#pragma unroll
        for (int j = 0; j < 4; j++) {
            ulonglong2 t2 = *(const ulonglong2*)(W + (size_t)(n0 + j) * IN_ + k4);
            wv[j][0] = t2.x; wv[j][1] = t2.y;
        }
#pragma unroll
        for (int i = 0; i < 4; i++) {
            ulonglong2 xv = *(const ulonglong2*)&Xs[m0 + i][k4];
#pragma unroll
            for (int j = 0; j < 4; j++) {
                ffma2(acc[i][j], xv.x, wv[j][0]);
                ffma2(acc[i][j], xv.y, wv[j][1]);
            }
        }
    }

    float4 bs;
    bs.x = bih[n0 + 0] + bhh[n0 + 0];
    bs.y = bih[n0 + 1] + bhh[n0 + 1];
    bs.z = bih[n0 + 2] + bhh[n0 + 2];
    bs.w = bih[n0 + 3] + bhh[n0 + 3];
#pragma unroll
    for (int i = 0; i < 4; i++) {
        float4 o;
        float2 p;
        p = unpk(acc[i][0]); o.x = p.x + p.y + bs.x;
        p = unpk(acc[i][1]); o.y = p.x + p.y + bs.y;
        p = unpk(acc[i][2]); o.z = p.x + p.y + bs.z;
        p = unpk(acc[i][3]); o.w = p.x + p.y + bs.w;
        *(float4*)(g_xp + (mbase + m0 + i) * G_ + n0) = o;
    }
}

// ---------------- kernel 2: fused 2-layer LSTM recurrence + output head ----------------
// 128 CTAs x 256 threads, 2 batch rows per CTA.
// Thread tid: q = tid>>2 (UNIT 0..63), s = tid&3 (K split).
// Thread owns all four gates of unit q: rows {q, 64+q, 128+q, 192+q}.
//   Layer-1 dot:  k in [16s,16s+16) over h1prev.
//   Layer-2 dot:  k in [16s,16s+16) over h1new (w2i) AND over h2prev (w2h).
// The h2prev half (P2a) is computed BEFORE barrier B1 (depends only on prev
// state) and overlaps the cell-1 MUFU chain; only the h1new half (P2b) sits on
// the post-B1 serial path. Gate sums allreduced with 2-level shfl over s; cell
// updates happen locally. 2 barriers per step.
__global__ __launch_bounds__(256, 1) void lstm_rec(
    const float* __restrict__ Whh1, const float* __restrict__ Wih2,
    const float* __restrict__ Whh2, const float* __restrict__ bih2,
    const float* __restrict__ bhh2, const float* __restrict__ Wout,
    const float* __restrict__ bout, float* __restrict__ out) {
    __shared__ float h1s[2][2][64];   // [parity][row][unit]
    __shared__ float h2s[2][2][64];
    __shared__ float red[16];         // [warp][row]

    int tid = threadIdx.x;
    int q = tid >> 2, s = tid & 3;
    int myrow = s & 1;

    // ---- weights into registers (gate-interleaved rows, k in [16s,16s+16)) ----
    u64 w1[4][8], w2i[4][8], w2h[4][8];
#pragma unroll
    for (int g = 0; g < 4; g++) {
        const u64* p;
        p = (const u64*)(Whh1 + (size_t)(g * 64 + q) * 64 + s * 16);
#pragma unroll
        for (int j = 0; j < 8; j++) w1[g][j] = p[j];
        p = (const u64*)(Wih2 + (size_t)(g * 64 + q) * 64 + s * 16);
#pragma unroll
        for (int j = 0; j < 8; j++) w2i[g][j] = p[j];
        p = (const u64*)(Whh2 + (size_t)(g * 64 + q) * 64 + s * 16);
#pragma unroll
        for (int j = 0; j < 8; j++) w2h[g][j] = p[j];
    }
    float b2v = bih2[s * 64 + q] + bhh2[s * 64 + q];   // bias of gate s*64+q
    float wo = Wout[q];
    float bo = bout[0];
    float c1 = 0.0f, c2 = 0.0f;                        // carries for row = myrow

    int b0 = blockIdx.x * 2;
    const float* xp0 = g_xp + (size_t)b0 * T_ * G_ + s * 64 + q;   // gate s*64+q
    const float* xp1 = xp0 + (size_t)T_ * G_;
    float xq0 = xp0[0];
    float xq1 = xp1[0];

    if (tid < 128) {                  // zero parity-1 (prv at t=0)
        h1s[1][tid >> 6][tid & 63] = 0.0f;
        h2s[1][tid >> 6][tid & 63] = 0.0f;
    }
    __syncthreads();

    for (int t = 0; t < T_; t++) {
        int cur = t & 1, prv = cur ^ 1;

        // ---- P1: layer-1 recurrent gate partial dots (h1 prev) ----
        u64 a[8];   // [2*gate + row]
#pragma unroll
        for (int i = 0; i < 8; i++) a[i] = 0ull;
        {
            const ulonglong2* hA = (const ulonglong2*)&h1s[prv][0][s * 16];
            const ulonglong2* hB = (const ulonglong2*)&h1s[prv][1][s * 16];
#pragma unroll
            for (int j = 0; j < 4; j++) {
                ulonglong2 u0 = hA[j];
                ulonglong2 u1 = hB[j];
#pragma unroll
                for (int g = 0; g < 4; g++) {
                    ffma2(a[2 * g + 0], w1[g][2 * j], u0.x);
                    ffma2(a[2 * g + 0], w1[g][2 * j + 1], u0.y);
                    ffma2(a[2 * g + 1], w1[g][2 * j], u1.x);
                    ffma2(a[2 * g + 1], w1[g][2 * j + 1], u1.y);
                }
            }
        }
        float v[8];
#pragma unroll
        for (int i = 0; i < 8; i++) { float2 f = unpk(a[i]); v[i] = f.x + f.y; }
        // fold xp in once (lane s owns gate s); allreduce distributes it
#pragma unroll
        for (int g = 0; g < 4; g++) {
            v[2 * g + 0] += (s == g) ? xq0 : 0.0f;
            v[2 * g + 1] += (s == g) ? xq1 : 0.0f;
        }
#pragma unroll
        for (int i = 0; i < 8; i++) {
            v[i] += __shfl_xor_sync(0xffffffffu, v[i], 1);
            v[i] += __shfl_xor_sync(0xffffffffu, v[i], 2);
        }
        if (t + 1 < T_) {             // prefetch next step's xp (2 regs only)
            xq0 = xp0[(size_t)(t + 1) * G_];
            xq1 = xp1[(size_t)(t + 1) * G_];
        }

        // ---- cell-1 update (row = myrow) ----
        float h1v;
        {
            float gi = myrow ? v[1] : v[0];
            float gf = myrow ? v[3] : v[2];
            float gg = myrow ? v[5] : v[4];
            float go = myrow ? v[7] : v[6];
            float iv = sigf(gi), fv = sigf(gf), gv = tanhf_(gg), ov = sigf(go);
            c1 = fv * c1 + iv * gv;
            h1v = ov * tanhf_(c1);
        }

        // ---- P2a: layer-2 partial dots over h2 PREV (independent of cell-1;
        //           fills the MUFU stall shadow above) ----
#pragma unroll
        for (int i = 0; i < 8; i++) a[i] = 0ull;
        {
            const ulonglong2* hA = (const ulonglong2*)&h2s[prv][0][s * 16];
            const ulonglong2* hB = (const ulonglong2*)&h2s[prv][1][s * 16];
#pragma unroll
            for (int j = 0; j < 4; j++) {
                ulonglong2 u0 = hA[j];
                ulonglong2 u1 = hB[j];
#pragma unroll
                for (int g = 0; g < 4; g++) {
                    ffma2(a[2 * g + 0], w2h[g][2 * j], u0.x);
                    ffma2(a[2 * g + 0], w2h[g][2 * j + 1], u0.y);
                    ffma2(a[2 * g + 1], w2h[g][2 * j], u1.x);
                    ffma2(a[2 * g + 1], w2h[g][2 * j + 1], u1.y);
                }
            }
        }
        if (s < 2) h1s[cur][s][q] = h1v;
        __syncthreads();              // B1: h1(cur) visible

        // ---- P2b: accumulate layer-2 dots over h1 NEW ----
        {
            const ulonglong2* hA = (const ulonglong2*)&h1s[cur][0][s * 16];
            const ulonglong2* hB = (const ulonglong2*)&h1s[cur][1][s * 16];
#pragma unroll
            for (int j = 0; j < 4; j++) {
                ulonglong2 u0 = hA[j];
                ulonglong2 u1 = hB[j];
#pragma unroll
                for (int g = 0; g < 4; g++) {
                    ffma2(a[2 * g + 0], w2i[g][2 * j], u0.x);
                    ffma2(a[2 * g + 0], w2i[g][2 * j + 1], u0.y);
                    ffma2(a[2 * g + 1], w2i[g][2 * j], u1.x);
                    ffma2(a[2 * g + 1], w2i[g][2 * j + 1], u1.y);
                }
            }
        }
#pragma unroll
        for (int i = 0; i < 8; i++) { float2 f = unpk(a[i]); v[i] = f.x + f.y; }
#pragma unroll
        for (int g = 0; g < 4; g++) {
            float bb = (s == g) ? b2v : 0.0f;
            v[2 * g + 0] += bb;
            v[2 * g + 1] += bb;
        }
#pragma unroll
        for (int i = 0; i < 8; i++) {
            v[i] += __shfl_xor_sync(0xffffffffu, v[i], 1);
            v[i] += __shfl_xor_sync(0xffffffffu, v[i], 2);
        }

        // ---- cell-2 update + output head ----
        {
            float gi = myrow ? v[1] : v[0];
            float gf = myrow ? v[3] : v[2];
            float gg = myrow ? v[5] : v[4];
            float go = myrow ? v[7] : v[6];
            float iv = sigf(gi), fv = sigf(gf), gv = tanhf_(gg), ov = sigf(go);
            c2 = fv * c2 + iv * gv;
            float h2v = ov * tanhf_(c2);
            if (s < 2) h2s[cur][s][q] = h2v;
            // head partial: reduce over the 8 units in this warp (lane bits 2-4)
            float p = wo * h2v;
            p += __shfl_xor_sync(0xffffffffu, p, 4);
            p += __shfl_xor_sync(0xffffffffu, p, 8);
            p += __shfl_xor_sync(0xffffffffu, p, 16);
            if ((tid & 31) < 2) red[(tid >> 5) * 2 + s] = p;
        }
        __syncthreads();              // B2: h2(cur) + red visible

        if (tid < 2) {
            float r = bo;
#pragma unroll
            for (int w = 0; w < 8; w++) r += red[w * 2 + tid];
            r = fminf(fmaxf(r, 0.0f), 1.0f);
            out[(size_t)(b0 + tid) * T_ + t] = r;
        }
    }
}

// ---------------- launch ----------------
extern "C" void kernel_launch(void* const* d_in, const int* in_sizes, int n_in,
                              void* d_out, int out_size) {
    const float* x    = (const float*)d_in[0];
    const float* Wih1 = (const float*)d_in[1];
    const float* Whh1 = (const float*)d_in[2];
    const float* bih1 = (const float*)d_in[3];
    const float* bhh1 = (const float*)d_in[4];
    const float* Wih2 = (const float*)d_in[5];
    const float* Whh2 = (const float*)d_in[6];
    const float* bih2 = (const float*)d_in[7];
    const float* bhh2 = (const float*)d_in[8];
    const float* Wout = (const float*)d_in[9];
    const float* bout = (const float*)d_in[10];
    float* out = (float*)d_out;

    xp_gemm<<<dim3((B_ * T_) / 64, G_ / 64), 256>>>(x, Wih1, bih1, bhh1);
    lstm_rec<<<128, 256>>>(Whh1, Wih2, Whh2, bih2, bhh2, Wout, bout, out);
    (void)in_sizes; (void)n_in; (void)out_size;
}

// round 8
// speedup vs baseline: 1.8507x; 1.8507x over previous
#include <cuda_runtime.h>
#include <cstdint>

#define B_   256
#define T_   2048
#define IN_  128
#define H_   64
#define G_   256   // 4*H

// Scratch (allocation-free rule: static __device__ array)
__device__ float g_xp[(size_t)B_ * T_ * G_];   // precomputed x@W_ih1^T + b_ih1 + b_hh1

typedef unsigned long long u64;

// ---------------- helpers ----------------
__device__ __forceinline__ void ffma2(u64& d, u64 a, u64 b) {
    asm("fma.rn.f32x2 %0, %1, %2, %0;" : "+l"(d) : "l"(a), "l"(b));
}
__device__ __forceinline__ float2 unpk(u64 p) {
    float2 r;
    asm("mov.b64 {%0, %1}, %2;" : "=f"(r.x), "=f"(r.y) : "l"(p));
    return r;
}
__device__ __forceinline__ float sigf(float x) {
    return __fdividef(1.0f, 1.0f + __expf(-x));
}
__device__ __forceinline__ float tanhf_(float x) {
    float a = fabsf(x);
    float e = __expf(2.0f * a);                 // inf-safe
    float r = 1.0f - __fdividef(2.0f, e + 1.0f);
    return copysignf(r, x);
}

// ---------------- kernel 1: xp = x @ W_ih1^T + b_ih1 + b_hh1 ----------------
// W tile staged in smem (k-contiguous rows, pitch 132 -> 2-way max conflicts,
// n = tx + 16j lane mapping); x read via broadcast LDG.128 (L2-resident).
// M = B*T, N = 256, K = 128. BM=64, BN=64, 256 threads, 4m x 4n per thread,
// k-paired f32x2 accumulation: 32 FFMA2 per 8 loads.
__global__ __launch_bounds__(256) void xp_gemm(const float* __restrict__ x,
                                               const float* __restrict__ W,
                                               const float* __restrict__ bih,
                                               const float* __restrict__ bhh) {
    __shared__ float Ws[64][132];              // 33 KB
    int tid = threadIdx.x;
    size_t mbase = (size_t)blockIdx.x * 64;
    int nbase = blockIdx.y * 64;

    // stage W tile: rows nbase..nbase+64, coalesced
#pragma unroll
    for (int i = 0; i < 8; i++) {
        int idx = tid + i * 256;
        int r = idx >> 5, c4 = (idx & 31) << 2;
        *(float4*)&Ws[r][c4] = *(const float4*)(W + (size_t)(nbase + r) * IN_ + c4);
    }
    __syncthreads();

    int tx = tid & 15, ty = tid >> 4;
    int m0 = ty * 4;
    const float* xg = x + (mbase + m0) * IN_;

    u64 acc[4][4];   // [m][j], k-paired
#pragma unroll
    for (int i = 0; i < 4; i++)
#pragma unroll
        for (int j = 0; j < 4; j++) acc[i][j] = 0ull;

#pragma unroll 4
    for (int k4 = 0; k4 < IN_; k4 += 4) {      // 32 iters, 4 k per iter
        u64 wv[4][2];
#pragma unroll
        for (int j = 0; j < 4; j++) {
            ulonglong2 t2 = *(const ulonglong2*)&Ws[tx + 16 * j][k4];
            wv[j][0] = t2.x; wv[j][1] = t2.y;
        }
#pragma unroll
        for (int i = 0; i < 4; i++) {
            ulonglong2 xv = *(const ulonglong2*)(xg + (size_t)i * IN_ + k4);
#pragma unroll
            for (int j = 0; j < 4; j++) {
                ffma2(acc[i][j], xv.x, wv[j][0]);
                ffma2(acc[i][j], xv.y, wv[j][1]);
            }
        }
    }

#pragma unroll
    for (int j = 0; j < 4; j++) {
        int n = nbase + tx + 16 * j;
        float b = bih[n] + bhh[n];
#pragma unroll
        for (int i = 0; i < 4; i++) {
            float2 p = unpk(acc[i][j]);
            g_xp[(mbase + m0 + i) * G_ + n] = p.x + p.y + b;
        }
    }
}

// ---------------- kernel 2: fused 2-layer LSTM recurrence + output head ----------------
// 128 CTAs x 256 threads, 2 batch rows per CTA.
// Thread tid: q = tid>>2 (UNIT 0..63), s = tid&3 (K split).
// Thread owns all four gates of unit q: rows {q, 64+q, 128+q, 192+q}.
//   Layer-1 dot:  k in [16s,16s+16) over h1prev.
//   Layer-2 dot:  k in [16s,16s+16) over h1new (w2i) AND h2prev (w2h).
// P2a (h2prev half) runs BEFORE barrier B1, overlapping cell-1's MUFU chain.
// Row-aware butterfly: at xor-1 each lane sends its PARTNER's row value and
// keeps its own, so only 8 shfl per phase (not 16) and no post-selects.
// 2 barriers per step.
__global__ __launch_bounds__(256, 1) void lstm_rec(
    const float* __restrict__ Whh1, const float* __restrict__ Wih2,
    const float* __restrict__ Whh2, const float* __restrict__ bih2,
    const float* __restrict__ bhh2, const float* __restrict__ Wout,
    const float* __restrict__ bout, float* __restrict__ out) {
    __shared__ float h1s[2][2][64];   // [parity][row][unit]
    __shared__ float h2s[2][2][64];
    __shared__ float red[16];         // [warp][row]

    int tid = threadIdx.x;
    int q = tid >> 2, s = tid & 3;
    int myrow = s & 1;

    // ---- weights into registers (gate-interleaved rows, k in [16s,16s+16)) ----
    u64 w1[4][8], w2i[4][8], w2h[4][8];
#pragma unroll
    for (int g = 0; g < 4; g++) {
        const u64* p;
        p = (const u64*)(Whh1 + (size_t)(g * 64 + q) * 64 + s * 16);
#pragma unroll
        for (int j = 0; j < 8; j++) w1[g][j] = p[j];
        p = (const u64*)(Wih2 + (size_t)(g * 64 + q) * 64 + s * 16);
#pragma unroll
        for (int j = 0; j < 8; j++) w2i[g][j] = p[j];
        p = (const u64*)(Whh2 + (size_t)(g * 64 + q) * 64 + s * 16);
#pragma unroll
        for (int j = 0; j < 8; j++) w2h[g][j] = p[j];
    }
    float b2v = bih2[s * 64 + q] + bhh2[s * 64 + q];   // bias of gate s*64+q
    float wo = Wout[q];
    float bo = bout[0];
    float c1 = 0.0f, c2 = 0.0f;                        // carries for row = myrow

    int b0 = blockIdx.x * 2;
    const float* xp0 = g_xp + (size_t)b0 * T_ * G_ + s * 64 + q;   // gate s*64+q
    const float* xp1 = xp0 + (size_t)T_ * G_;
    float xq0 = xp0[0];
    float xq1 = xp1[0];

    if (tid < 128) {                  // zero parity-1 (prv at t=0)
        h1s[1][tid >> 6][tid & 63] = 0.0f;
        h2s[1][tid >> 6][tid & 63] = 0.0f;
    }
    __syncthreads();

    for (int t = 0; t < T_; t++) {
        int cur = t & 1, prv = cur ^ 1;

        // ---- P1: layer-1 recurrent gate partial dots (h1 prev) ----
        u64 a[8];   // [2*gate + row]
#pragma unroll
        for (int i = 0; i < 8; i++) a[i] = 0ull;
        {
            const ulonglong2* hA = (const ulonglong2*)&h1s[prv][0][s * 16];
            const ulonglong2* hB = (const ulonglong2*)&h1s[prv][1][s * 16];
#pragma unroll
            for (int j = 0; j < 4; j++) {
                ulonglong2 u0 = hA[j];
                ulonglong2 u1 = hB[j];
#pragma unroll
                for (int g = 0; g < 4; g++) {
                    ffma2(a[2 * g + 0], w1[g][2 * j], u0.x);
                    ffma2(a[2 * g + 0], w1[g][2 * j + 1], u0.y);
                    ffma2(a[2 * g + 1], w1[g][2 * j], u1.x);
                    ffma2(a[2 * g + 1], w1[g][2 * j + 1], u1.y);
                }
            }
        }
        float v[8];
#pragma unroll
        for (int i = 0; i < 8; i++) { float2 f = unpk(a[i]); v[i] = f.x + f.y; }
        // fold xp in once (lane s owns gate s); reduction distributes it
#pragma unroll
        for (int g = 0; g < 4; g++) {
            v[2 * g + 0] += (s == g) ? xq0 : 0.0f;
            v[2 * g + 1] += (s == g) ? xq1 : 0.0f;
        }
        // row-aware butterfly: w[g] = full gate-g sum for row = myrow
        float wv[4];
#pragma unroll
        for (int g = 0; g < 4; g++) {
            float snd = myrow ? v[2 * g + 0] : v[2 * g + 1];   // partner's row
            float own = myrow ? v[2 * g + 1] : v[2 * g + 0];
            float tt = own + __shfl_xor_sync(0xffffffffu, snd, 1);
            tt += __shfl_xor_sync(0xffffffffu, tt, 2);
            wv[g] = tt;
        }
        if (t + 1 < T_) {             // prefetch next step's xp (2 regs only)
            xq0 = xp0[(size_t)(t + 1) * G_];
            xq1 = xp1[(size_t)(t + 1) * G_];
        }

        // ---- cell-1 update (row = myrow) ----
        float h1v;
        {
            float iv = sigf(wv[0]), fv = sigf(wv[1]);
            float gv = tanhf_(wv[2]), ov = sigf(wv[3]);
            c1 = fv * c1 + iv * gv;
            h1v = ov * tanhf_(c1);
        }

        // ---- P2a: layer-2 partial dots over h2 PREV (independent of cell-1;
        //           fills the MUFU stall shadow above) ----
#pragma unroll
        for (int i = 0; i < 8; i++) a[i] = 0ull;
        {
            const ulonglong2* hA = (const ulonglong2*)&h2s[prv][0][s * 16];
            const ulonglong2* hB = (const ulonglong2*)&h2s[prv][1][s * 16];
#pragma unroll
            for (int j = 0; j < 4; j++) {
                ulonglong2 u0 = hA[j];
                ulonglong2 u1 = hB[j];
#pragma unroll
                for (int g = 0; g < 4; g++) {
                    ffma2(a[2 * g + 0], w2h[g][2 * j], u0.x);
                    ffma2(a[2 * g + 0], w2h[g][2 * j + 1], u0.y);
                    ffma2(a[2 * g + 1], w2h[g][2 * j], u1.x);
                    ffma2(a[2 * g + 1], w2h[g][2 * j + 1], u1.y);
                }
            }
        }
        if (s < 2) h1s[cur][s][q] = h1v;
        __syncthreads();              // B1: h1(cur) visible

        // ---- P2b: accumulate layer-2 dots over h1 NEW ----
        {
            const ulonglong2* hA = (const ulonglong2*)&h1s[cur][0][s * 16];
            const ulonglong2* hB = (const ulonglong2*)&h1s[cur][1][s * 16];
#pragma unroll
            for (int j = 0; j < 4; j++) {
                ulonglong2 u0 = hA[j];
                ulonglong2 u1 = hB[j];
#pragma unroll
                for (int g = 0; g < 4; g++) {
                    ffma2(a[2 * g + 0], w2i[g][2 * j], u0.x);
                    ffma2(a[2 * g + 0], w2i[g][2 * j + 1], u0.y);
                    ffma2(a[2 * g + 1], w2i[g][2 * j], u1.x);
                    ffma2(a[2 * g + 1], w2i[g][2 * j + 1], u1.y);
                }
            }
        }
#pragma unroll
        for (int i = 0; i < 8; i++) { float2 f = unpk(a[i]); v[i] = f.x + f.y; }
#pragma unroll
        for (int g = 0; g < 4; g++) {
            float bb = (s == g) ? b2v : 0.0f;
            v[2 * g + 0] += bb;
            v[2 * g + 1] += bb;
        }
#pragma unroll
        for (int g = 0; g < 4; g++) {
            float snd = myrow ? v[2 * g + 0] : v[2 * g + 1];
            float own = myrow ? v[2 * g + 1] : v[2 * g + 0];
            float tt = own + __shfl_xor_sync(0xffffffffu, snd, 1);
            tt += __shfl_xor_sync(0xffffffffu, tt, 2);
            wv[g] = tt;
        }

        // ---- cell-2 update + output head ----
        {
            float iv = sigf(wv[0]), fv = sigf(wv[1]);
            float gv = tanhf_(wv[2]), ov = sigf(wv[3]);
            c2 = fv * c2 + iv * gv;
            float h2v = ov * tanhf_(c2);
            if (s < 2) h2s[cur][s][q] = h2v;
            // head partial: reduce over the 8 units in this warp (lane bits 2-4)
            float p = wo * h2v;
            p += __shfl_xor_sync(0xffffffffu, p, 4);
            p += __shfl_xor_sync(0xffffffffu, p, 8);
            p += __shfl_xor_sync(0xffffffffu, p, 16);
            if ((tid & 31) < 2) red[(tid >> 5) * 2 + s] = p;
        }
        __syncthreads();              // B2: h2(cur) + red visible

        if (tid < 2) {
            float r = bo;
#pragma unroll
            for (int w = 0; w < 8; w++) r += red[w * 2 + tid];
            r = fminf(fmaxf(r, 0.0f), 1.0f);
            out[(size_t)(b0 + tid) * T_ + t] = r;
        }
    }
}

// ---------------- launch ----------------
extern "C" void kernel_launch(void* const* d_in, const int* in_sizes, int n_in,
                              void* d_out, int out_size) {
    const float* x    = (const float*)d_in[0];
    const float* Wih1 = (const float*)d_in[1];
    const float* Whh1 = (const float*)d_in[2];
    const float* bih1 = (const float*)d_in[3];
    const float* bhh1 = (const float*)d_in[4];
    const float* Wih2 = (const float*)d_in[5];
    const float* Whh2 = (const float*)d_in[6];
    const float* bih2 = (const float*)d_in[7];
    const float* bhh2 = (const float*)d_in[8];
    const float* Wout = (const float*)d_in[9];
    const float* bout = (const float*)d_in[10];
    float* out = (float*)d_out;

    xp_gemm<<<dim3((B_ * T_) / 64, G_ / 64), 256>>>(x, Wih1, bih1, bhh1);
    lstm_rec<<<128, 256>>>(Whh1, Wih2, Whh2, bih2, bhh2, Wout, bout, out);
    (void)in_sizes; (void)n_in; (void)out_size;
}

// round 10
// speedup vs baseline: 2.1567x; 1.1653x over previous
#include <cuda_runtime.h>
#include <cstdint>

#define B_   256
#define T_   2048
#define IN_  128
#define H_   64
#define G_   256   // 4*H

// Scratch (allocation-free rule: static __device__ array)
__device__ float g_xp[(size_t)B_ * T_ * G_];   // precomputed x@W_ih1^T + b_ih1 + b_hh1

typedef unsigned long long u64;

// ---------------- helpers ----------------
__device__ __forceinline__ void ffma2(u64& d, u64 a, u64 b) {
    asm("fma.rn.f32x2 %0, %1, %2, %0;" : "+l"(d) : "l"(a), "l"(b));
}
__device__ __forceinline__ float2 unpk(u64 p) {
    float2 r;
    asm("mov.b64 {%0, %1}, %2;" : "=f"(r.x), "=f"(r.y) : "l"(p));
    return r;
}
__device__ __forceinline__ float sigf(float x) {
    return __fdividef(1.0f, 1.0f + __expf(-x));
}
__device__ __forceinline__ float tanhf_(float x) {
    float a = fabsf(x);
    float e = __expf(2.0f * a);                 // inf-safe
    float r = 1.0f - __fdividef(2.0f, e + 1.0f);
    return copysignf(r, x);
}

// ---------------- kernel 1: xp = x @ W_ih1^T + b_ih1 + b_hh1 ----------------
// (unchanged from R8 — W tile staged in smem, broadcast LDG.128 for x)
__global__ __launch_bounds__(256) void xp_gemm(const float* __restrict__ x,
                                               const float* __restrict__ W,
                                               const float* __restrict__ bih,
                                               const float* __restrict__ bhh) {
    __shared__ float Ws[64][132];              // 33 KB
    int tid = threadIdx.x;
    size_t mbase = (size_t)blockIdx.x * 64;
    int nbase = blockIdx.y * 64;

#pragma unroll
    for (int i = 0; i < 8; i++) {
        int idx = tid + i * 256;
        int r = idx >> 5, c4 = (idx & 31) << 2;
        *(float4*)&Ws[r][c4] = *(const float4*)(W + (size_t)(nbase + r) * IN_ + c4);
    }
    __syncthreads();

    int tx = tid & 15, ty = tid >> 4;
    int m0 = ty * 4;
    const float* xg = x + (mbase + m0) * IN_;

    u64 acc[4][4];
#pragma unroll
    for (int i = 0; i < 4; i++)
#pragma unroll
        for (int j = 0; j < 4; j++) acc[i][j] = 0ull;

#pragma unroll 4
    for (int k4 = 0; k4 < IN_; k4 += 4) {
        u64 wv[4][2];
#pragma unroll
        for (int j = 0; j < 4; j++) {
            ulonglong2 t2 = *(const ulonglong2*)&Ws[tx + 16 * j][k4];
            wv[j][0] = t2.x; wv[j][1] = t2.y;
        }
#pragma unroll
        for (int i = 0; i < 4; i++) {
            ulonglong2 xv = *(const ulonglong2*)(xg + (size_t)i * IN_ + k4);
#pragma unroll
            for (int j = 0; j < 4; j++) {
                ffma2(acc[i][j], xv.x, wv[j][0]);
                ffma2(acc[i][j], xv.y, wv[j][1]);
            }
        }
    }

#pragma unroll
    for (int j = 0; j < 4; j++) {
        int n = nbase + tx + 16 * j;
        float b = bih[n] + bhh[n];
#pragma unroll
        for (int i = 0; i < 4; i++) {
            float2 p = unpk(acc[i][j]);
            g_xp[(mbase + m0 + i) * G_ + n] = p.x + p.y + b;
        }
    }
}

// ---------------- kernel 2: fused 2-layer LSTM recurrence + output head ----------------
// 128 CTAs x 256 threads, 2 batch rows per CTA.
// Thread (q = tid>>2: unit; s = tid&3: k-split). Gate-interleaved weight rows.
// SOFTWARE-PIPELINED: loop carries wv1[] = reduced layer-1 gate sums for step t.
//   body(t): cell1 | P2a (h2 prev) | store h1 | B1 |
//            fused pass over h1new: P2b accs + P1(t+1) accs share LDS operands |
//            reduce P2 -> cell2, store h2, head | reduce P1 -> wv1(t+1) | B2 | out(t)
__global__ __launch_bounds__(256, 1) void lstm_rec(
    const float* __restrict__ Whh1, const float* __restrict__ Wih2,
    const float* __restrict__ Whh2, const float* __restrict__ bih2,
    const float* __restrict__ bhh2, const float* __restrict__ Wout,
    const float* __restrict__ bout, float* __restrict__ out) {
    __shared__ float h1s[2][2][64];   // [parity][row][unit]
    __shared__ float h2s[2][2][64];
    __shared__ float red[16];         // [warp][row]

    int tid = threadIdx.x;
    int q = tid >> 2, s = tid & 3;
    int myrow = s & 1;

    // ---- weights into registers (gate-interleaved rows, k in [16s,16s+16)) ----
    u64 w1[4][8], w2i[4][8], w2h[4][8];
#pragma unroll
    for (int g = 0; g < 4; g++) {
        const u64* p;
        p = (const u64*)(Whh1 + (size_t)(g * 64 + q) * 64 + s * 16);
#pragma unroll
        for (int j = 0; j < 8; j++) w1[g][j] = p[j];
        p = (const u64*)(Wih2 + (size_t)(g * 64 + q) * 64 + s * 16);
#pragma unroll
        for (int j = 0; j < 8; j++) w2i[g][j] = p[j];
        p = (const u64*)(Whh2 + (size_t)(g * 64 + q) * 64 + s * 16);
#pragma unroll
        for (int j = 0; j < 8; j++) w2h[g][j] = p[j];
    }
    float b2v = bih2[s * 64 + q] + bhh2[s * 64 + q];   // bias of gate s*64+q
    float wo = Wout[q];
    float bo = bout[0];
    float c1 = 0.0f, c2 = 0.0f;                        // carries for row = myrow

    int b0 = blockIdx.x * 2;
    const float* xp0 = g_xp + (size_t)b0 * T_ * G_ + s * 64 + q;   // gate s*64+q
    const float* xp1 = xp0 + (size_t)T_ * G_;
    float xq0 = xp0[0];
    float xq1 = xp1[0];

    if (tid < 128) {                  // zero parity-1 (prv at t=0)
        h1s[1][tid >> 6][tid & 63] = 0.0f;
        h2s[1][tid >> 6][tid & 63] = 0.0f;
    }
    __syncthreads();

    // ---- prologue: wv1(0). h = 0 so layer-1 gates(0) = xp(0) distributed ----
    float wv1[4];
#pragma unroll
    for (int g = 0; g < 4; g++) {
        float f0 = (s == g) ? xq0 : 0.0f;   // row 0 partial
        float f1 = (s == g) ? xq1 : 0.0f;   // row 1 partial
        float snd = myrow ? f0 : f1;
        float own = myrow ? f1 : f0;
        float tt = own + __shfl_xor_sync(0xffffffffu, snd, 1);
        tt += __shfl_xor_sync(0xffffffffu, tt, 2);
        wv1[g] = tt;
    }

    for (int t = 0; t < T_; t++) {
        int cur = t & 1, prv = cur ^ 1;

        // ---- cell-1 update from carried wv1 ----
        float h1v;
        {
            float iv = sigf(wv1[0]), fv = sigf(wv1[1]);
            float gv = tanhf_(wv1[2]), ov = sigf(wv1[3]);
            c1 = fv * c1 + iv * gv;
            h1v = ov * tanhf_(c1);
        }

        // ---- P2a: layer-2 dots over h2 PREV (fills cell-1 MUFU shadow) ----
        u64 a[8];   // [2*gate + row]
#pragma unroll
        for (int i = 0; i < 8; i++) a[i] = 0ull;
        {
            const ulonglong2* hA = (const ulonglong2*)&h2s[prv][0][s * 16];
            const ulonglong2* hB = (const ulonglong2*)&h2s[prv][1][s * 16];
#pragma unroll
            for (int j = 0; j < 4; j++) {
                ulonglong2 u0 = hA[j];
                ulonglong2 u1 = hB[j];
#pragma unroll
                for (int g = 0; g < 4; g++) {
                    ffma2(a[2 * g + 0], w2h[g][2 * j], u0.x);
                    ffma2(a[2 * g + 0], w2h[g][2 * j + 1], u0.y);
                    ffma2(a[2 * g + 1], w2h[g][2 * j], u1.x);
                    ffma2(a[2 * g + 1], w2h[g][2 * j + 1], u1.y);
                }
            }
        }
        // prefetch xp(t+1); consumed at the P1 reduce below (post-B1)
        if (t + 1 < T_) {
            xq0 = xp0[(size_t)(t + 1) * G_];
            xq1 = xp1[(size_t)(t + 1) * G_];
        }
        if (s < 2) h1s[cur][s][q] = h1v;
        __syncthreads();              // B1: h1(cur) visible

        // ---- fused pass over h1 NEW: P2b (into a) + P1(t+1) (into b) ----
        u64 b[8];
#pragma unroll
        for (int i = 0; i < 8; i++) b[i] = 0ull;
        {
            const ulonglong2* hA = (const ulonglong2*)&h1s[cur][0][s * 16];
            const ulonglong2* hB = (const ulonglong2*)&h1s[cur][1][s * 16];
#pragma unroll
            for (int j = 0; j < 4; j++) {
                ulonglong2 u0 = hA[j];
                ulonglong2 u1 = hB[j];
#pragma unroll
                for (int g = 0; g < 4; g++) {
                    ffma2(a[2 * g + 0], w2i[g][2 * j], u0.x);
                    ffma2(a[2 * g + 0], w2i[g][2 * j + 1], u0.y);
                    ffma2(a[2 * g + 1], w2i[g][2 * j], u1.x);
                    ffma2(a[2 * g + 1], w2i[g][2 * j + 1], u1.y);
                }
#pragma unroll
                for (int g = 0; g < 4; g++) {
                    ffma2(b[2 * g + 0], w1[g][2 * j], u0.x);
                    ffma2(b[2 * g + 0], w1[g][2 * j + 1], u0.y);
                    ffma2(b[2 * g + 1], w1[g][2 * j], u1.x);
                    ffma2(b[2 * g + 1], w1[g][2 * j + 1], u1.y);
                }
            }
        }

        // ---- reduce P2 (fold bias2 pre-reduction, ONLY from lane s==g) -> wv2 ----
        float wv2[4];
#pragma unroll
        for (int g = 0; g < 4; g++) {
            float bb = (s == g) ? b2v : 0.0f;      // FIX: guard restored
            float2 f0 = unpk(a[2 * g + 0]);
            float2 f1 = unpk(a[2 * g + 1]);
            float v0 = f0.x + f0.y + bb;
            float v1 = f1.x + f1.y + bb;
            float snd = myrow ? v0 : v1;
            float own = myrow ? v1 : v0;
            float tt = own + __shfl_xor_sync(0xffffffffu, snd, 1);
            tt += __shfl_xor_sync(0xffffffffu, tt, 2);
            wv2[g] = tt;
        }

        // ---- reduce P1 (fold xp(t+1) pre-reduction) -> wv1 for next step ----
        // (at t = T-1 this produces garbage that is never consumed)
#pragma unroll
        for (int g = 0; g < 4; g++) {
            float2 f0 = unpk(b[2 * g + 0]);
            float2 f1 = unpk(b[2 * g + 1]);
            float v0 = f0.x + f0.y + ((s == g) ? xq0 : 0.0f);
            float v1 = f1.x + f1.y + ((s == g) ? xq1 : 0.0f);
            float snd = myrow ? v0 : v1;
            float own = myrow ? v1 : v0;
            float tt = own + __shfl_xor_sync(0xffffffffu, snd, 1);
            tt += __shfl_xor_sync(0xffffffffu, tt, 2);
            wv1[g] = tt;
        }

        // ---- cell-2 update + output head ----
        {
            float iv = sigf(wv2[0]), fv = sigf(wv2[1]);
            float gv = tanhf_(wv2[2]), ov = sigf(wv2[3]);
            c2 = fv * c2 + iv * gv;
            float h2v = ov * tanhf_(c2);
            if (s < 2) h2s[cur][s][q] = h2v;
            float p = wo * h2v;
            p += __shfl_xor_sync(0xffffffffu, p, 4);
            p += __shfl_xor_sync(0xffffffffu, p, 8);
            p += __shfl_xor_sync(0xffffffffu, p, 16);
            if ((tid & 31) < 2) red[(tid >> 5) * 2 + s] = p;
        }
        __syncthreads();              // B2: h2(cur) + red visible

        if (tid < 2) {
            float r = bo;
#pragma unroll
            for (int w = 0; w < 8; w++) r += red[w * 2 + tid];
            r = fminf(fmaxf(r, 0.0f), 1.0f);
            out[(size_t)(b0 + tid) * T_ + t] = r;
        }
    }
}

// ---------------- launch ----------------
extern "C" void kernel_launch(void* const* d_in, const int* in_sizes, int n_in,
                              void* d_out, int out_size) {
    const float* x    = (const float*)d_in[0];
    const float* Wih1 = (const float*)d_in[1];
    const float* Whh1 = (const float*)d_in[2];
    const float* bih1 = (const float*)d_in[3];
    const float* bhh1 = (const float*)d_in[4];
    const float* Wih2 = (const float*)d_in[5];
    const float* Whh2 = (const float*)d_in[6];
    const float* bih2 = (const float*)d_in[7];
    const float* bhh2 = (const float*)d_in[8];
    const float* Wout = (const float*)d_in[9];
    const float* bout = (const float*)d_in[10];
    float* out = (float*)d_out;

    xp_gemm<<<dim3((B_ * T_) / 64, G_ / 64), 256>>>(x, Wih1, bih1, bhh1);
    lstm_rec<<<128, 256>>>(Whh1, Wih2, Whh2, bih2, bhh2, Wout, bout, out);
    (void)in_sizes; (void)n_in; (void)out_size;
}